// round 10
// baseline (speedup 1.0000x reference)
#include <cuda_runtime.h>
#include <cuda_bf16.h>
#include <cstdint>

// ---------------- problem constants ----------------
#define BATCH    256
#define FEAT     1500
#define FEAT_PAD 1536          // 48 * 32, padded K for decoder (zero-filled)
#define INSZ     28224
#define SPLITK   12
#define ENC_KBLK_TOTAL 882     // 28224 / 32
#define ENC_KBLK_PER_SPLIT 74  // 11*74 + 68 = 882
#define DEC_KBLK 48            // 1536 / 32

// ---------------- GEMM tile config -----------------
#define BM 128
#define BN 128
#define BK 32                  // K f32 elements per chunk = 128B per row
#define NTH 256                // 8 warps: 2 (M) x 4 (N), warp tile 64x32
#define STAGES 3

// smem: per stage, A tile [128 rows x 128B] + B tile [128 x 128B], f32,
// 32B-block XOR swizzle (block ^= row&3) -> cp.async 16B stores OK and the
// 8-row x 32B LDS.64 fragment pattern is phase-optimal.
#define TILE_B  16384
#define STAGE_B (2 * TILE_B)          // 32768
#define SMEM_TOTAL (STAGES * STAGE_B) // 98304; 2 CTAs = 192KB

// ---------------- scratch ----------------
__device__ float g_preact[SPLITK * BATCH * FEAT];      // 18.4 MB
__device__ float g_yenc[BATCH * FEAT_PAD];             // zero-padded cols
__device__ float g_rownorm2[FEAT];

// ---------------- helpers ----------------
__device__ __forceinline__ float sigmoidf_(float z) { return 1.0f / (1.0f + __expf(-z)); }

// swizzled byte offset within a tile: row-major 128B rows, 32B blocks XOR'd by row&3
__device__ __forceinline__ uint32_t swz(int row, int byte_in_row) {
    uint32_t blk = ((uint32_t)byte_in_row >> 5) ^ ((uint32_t)row & 3);
    return (uint32_t)row * 128 + (blk << 5) + ((uint32_t)byte_in_row & 31);
}

__device__ __forceinline__ void cpa16(void* dst_smem, const void* src, int sz) {
    uint32_t d;
    asm("{ .reg .u64 t; cvta.to.shared.u64 t, %1; cvt.u32.u64 %0, t; }" : "=r"(d) : "l"(dst_smem));
    asm volatile("cp.async.cg.shared.global [%0], [%1], 16, %2;" :: "r"(d), "l"(src), "r"(sz));
}
#define CP_COMMIT() asm volatile("cp.async.commit_group;" ::: "memory")
#define CP_WAIT1()  asm volatile("cp.async.wait_group 1;" ::: "memory")
#define CP_WAIT0()  asm volatile("cp.async.wait_group 0;" ::: "memory")

// split f32 pair (x=k, y=k+1) into packed bf16x2 hi and lo words (k in low half)
__device__ __forceinline__ void split_pair(float x, float y, uint32_t& hw, uint32_t& lw) {
    uint32_t h;
    asm("cvt.rn.bf16x2.f32 %0, %1, %2;" : "=r"(h) : "f"(y), "f"(x));
    float hx = __uint_as_float(h << 16);
    float hy = __uint_as_float(h & 0xffff0000u);
    float lx = x - hx, ly = y - hy;
    asm("cvt.rn.bf16x2.f32 %0, %1, %2;" : "=r"(lw) : "f"(ly), "f"(lx));
    hw = h;
}

__device__ __forceinline__ void mma16816(float c[4], const uint32_t a[4], uint32_t b0, uint32_t b1) {
    asm volatile(
        "mma.sync.aligned.m16n8k16.row.col.f32.bf16.bf16.f32 "
        "{%0,%1,%2,%3}, {%4,%5,%6,%7}, {%8,%9}, {%0,%1,%2,%3};"
        : "+f"(c[0]), "+f"(c[1]), "+f"(c[2]), "+f"(c[3])
        : "r"(a[0]), "r"(a[1]), "r"(a[2]), "r"(a[3]), "r"(b0), "r"(b1));
}

// ---------------------------------------------------------------------------
// split-bf16 HMMA GEMM, f32 tiles staged via cp.async, register-side split.
//   C[m,n] = sum_k A[m,k] * B[n,k]
//   mode 0: raw f32 partial -> C + z*BATCH*ldc        (encoder split-K)
//   mode 1: sigmoid(acc + bias[n]) -> C               (decoder)
// ---------------------------------------------------------------------------
__global__ void __launch_bounds__(NTH, 2)
gemm_hmma(const float* __restrict__ A, const float* __restrict__ B,
          const float* __restrict__ bias, float* __restrict__ C,
          int N, int lda, int ldb, int kvalidB, int ldc,
          int kblk_per_split, int kblk_total, int mode)
{
    extern __shared__ char smem[];
    const int tid = threadIdx.x, wid = tid >> 5, lane = tid & 31;
    const int bm = blockIdx.y * BM;
    const int bn = blockIdx.x * BN;
    const int z  = blockIdx.z;
    const int kb0 = z * kblk_per_split;
    int nch = kblk_total - kb0;
    if (nch > kblk_per_split) nch = kblk_per_split;
    if (nch <= 0) return;

    const int wm = wid >> 2;        // 0..1 -> m offset wm*64
    const int wn = wid & 3;         // 0..3 -> n offset wn*32

    // copy mapping: row = tid>>1 (0..127), 4 consecutive 16B units from (tid&1)*4
    const int crow = tid >> 1;
    const int cu0  = (tid & 1) * 4;
    const int gnB  = bn + crow;
    const int gnBc = gnB < N ? gnB : N - 1;

    float acc[4][4][4];
    #pragma unroll
    for (int i = 0; i < 4; i++)
        #pragma unroll
        for (int j = 0; j < 4; j++)
            #pragma unroll
            for (int q = 0; q < 4; q++) acc[i][j][q] = 0.f;

    // ---- copy issue (one chunk into one stage) ----
    auto issue_copy = [&](int c) {
        const int st = (c % STAGES);
        char* sA = smem + st * STAGE_B;
        char* sB = sA + TILE_B;
        const int kc = (kb0 + c) * BK;
        const float* srcA = A + (size_t)(bm + crow) * lda + kc;
        #pragma unroll
        for (int i = 0; i < 4; i++) {
            int u = cu0 + i;
            cpa16(sA + swz(crow, u * 16), srcA + u * 4, 16);
        }
        const float* srcB = B + (size_t)gnBc * ldb + kc;
        #pragma unroll
        for (int i = 0; i < 4; i++) {
            int u = cu0 + i;
            int ok = (gnB < N) && (kc + u * 4 < kvalidB);
            cpa16(sB + swz(crow, u * 16), ok ? (srcB + u * 4) : (const float*)B, ok ? 16 : 0);
        }
    };

    // ---- prologue: stages 0,1 ----
    if (0 < nch) issue_copy(0);
    CP_COMMIT();
    if (1 < nch) issue_copy(1);
    CP_COMMIT();

    const int fr = lane >> 2;          // fragment row/col within 8
    const int fk = (lane & 3) * 8;     // k byte offset (2 f32)

    for (int ci = 0; ci < nch; ci++) {
        CP_WAIT1();
        __syncthreads();

        if (ci + 2 < nch) issue_copy(ci + 2);
        CP_COMMIT();

        const char* sA = smem + (ci % STAGES) * STAGE_B;
        const char* sB = sA + TILE_B;

        #pragma unroll
        for (int ks = 0; ks < 2; ks++) {
            const int kb = ks * 64 + fk;
            // persistent B fragments for this kstep (hi+lo from same f32 data)
            uint32_t bh[4][2], bl[4][2];
            #pragma unroll
            for (int ni = 0; ni < 4; ni++) {
                int c = wn * 32 + ni * 8 + fr;
                float2 v0 = *reinterpret_cast<const float2*>(sB + swz(c, kb));
                float2 v1 = *reinterpret_cast<const float2*>(sB + swz(c, kb + 32));
                split_pair(v0.x, v0.y, bh[ni][0], bl[ni][0]);
                split_pair(v1.x, v1.y, bh[ni][1], bl[ni][1]);
            }
            #pragma unroll
            for (int mi = 0; mi < 4; mi++) {
                int r0 = wm * 64 + mi * 16 + fr;
                float2 v0 = *reinterpret_cast<const float2*>(sA + swz(r0,     kb));
                float2 v1 = *reinterpret_cast<const float2*>(sA + swz(r0 + 8, kb));
                float2 v2 = *reinterpret_cast<const float2*>(sA + swz(r0,     kb + 32));
                float2 v3 = *reinterpret_cast<const float2*>(sA + swz(r0 + 8, kb + 32));
                uint32_t ah[4], al[4];
                split_pair(v0.x, v0.y, ah[0], al[0]);
                split_pair(v1.x, v1.y, ah[1], al[1]);
                split_pair(v2.x, v2.y, ah[2], al[2]);
                split_pair(v3.x, v3.y, ah[3], al[3]);
                #pragma unroll
                for (int ni = 0; ni < 4; ni++)
                    mma16816(acc[mi][ni], ah, bh[ni][0], bh[ni][1]);
                #pragma unroll
                for (int ni = 0; ni < 4; ni++)
                    mma16816(acc[mi][ni], al, bh[ni][0], bh[ni][1]);
                #pragma unroll
                for (int ni = 0; ni < 4; ni++)
                    mma16816(acc[mi][ni], ah, bl[ni][0], bl[ni][1]);
            }
        }
    }
    CP_WAIT0();

    // ---- epilogue ----
    const int er = lane >> 2, ec = (lane & 3) * 2;
    #pragma unroll
    for (int mi = 0; mi < 4; mi++) {
        #pragma unroll
        for (int ni = 0; ni < 4; ni++) {
            int m0 = bm + wm * 64 + mi * 16 + er;
            int n0 = bn + wn * 32 + ni * 8 + ec;
            if (mode == 0) {
                float* Cz = C + (size_t)z * BATCH * ldc;
                if (n0 + 1 < N) {
                    *reinterpret_cast<float2*>(Cz + (size_t)m0 * ldc + n0) =
                        make_float2(acc[mi][ni][0], acc[mi][ni][1]);
                    *reinterpret_cast<float2*>(Cz + (size_t)(m0 + 8) * ldc + n0) =
                        make_float2(acc[mi][ni][2], acc[mi][ni][3]);
                } else if (n0 < N) {
                    Cz[(size_t)m0 * ldc + n0] = acc[mi][ni][0];
                    Cz[(size_t)(m0 + 8) * ldc + n0] = acc[mi][ni][2];
                }
            } else {
                if (n0 + 1 < N) {
                    float b0 = bias[n0], b1 = bias[n0 + 1];
                    *reinterpret_cast<float2*>(C + (size_t)m0 * ldc + n0) =
                        make_float2(sigmoidf_(acc[mi][ni][0] + b0), sigmoidf_(acc[mi][ni][1] + b1));
                    *reinterpret_cast<float2*>(C + (size_t)(m0 + 8) * ldc + n0) =
                        make_float2(sigmoidf_(acc[mi][ni][2] + b0), sigmoidf_(acc[mi][ni][3] + b1));
                } else if (n0 < N) {
                    float b0 = bias[n0];
                    C[(size_t)m0 * ldc + n0] = sigmoidf_(acc[mi][ni][0] + b0);
                    C[(size_t)(m0 + 8) * ldc + n0] = sigmoidf_(acc[mi][ni][2] + b0);
                }
            }
        }
    }
}

// ---------------------------------------------------------------------------
// row_norm2[f] = sum_i W_enc[f,i]^2 ; zero-init jac accumulator
// ---------------------------------------------------------------------------
__global__ void rownorm_kernel(const float* __restrict__ W, float* __restrict__ jac_init) {
    int f = blockIdx.x;
    const float4* row = reinterpret_cast<const float4*>(W + (size_t)f * INSZ);
    float s = 0.f;
    for (int i = threadIdx.x; i < INSZ / 4; i += blockDim.x) {
        float4 v = row[i];
        s += v.x * v.x + v.y * v.y + v.z * v.z + v.w * v.w;
    }
    __shared__ float red[256];
    red[threadIdx.x] = s;
    __syncthreads();
    for (int o = 128; o > 0; o >>= 1) {
        if (threadIdx.x < o) red[threadIdx.x] += red[threadIdx.x + o];
        __syncthreads();
    }
    if (threadIdx.x == 0) g_rownorm2[f] = red[0];
    if (blockIdx.x == 0 && threadIdx.x == 0) *jac_init = 0.f;
}

// ---------------------------------------------------------------------------
// encoder epilogue: sum split-K partials + bias -> sigmoid -> y_enc (padded),
// accumulate jac_reg
// ---------------------------------------------------------------------------
__global__ void enc_epilogue(const float* __restrict__ b_enc, float* __restrict__ jac_out) {
    int idx = blockIdx.x * blockDim.x + threadIdx.x;
    float part = 0.f;
    if (idx < BATCH * FEAT_PAD) {
        int m = idx / FEAT_PAD, f = idx % FEAT_PAD;
        if (f < FEAT) {
            float zsum = b_enc[f];
            int base = m * FEAT + f;
            #pragma unroll
            for (int s = 0; s < SPLITK; s++)
                zsum += g_preact[(size_t)s * BATCH * FEAT + base];
            float y = sigmoidf_(zsum);
            g_yenc[idx] = y;
            float sd = y * (1.f - y);
            part = sd * sd * g_rownorm2[f];
        } else {
            g_yenc[idx] = 0.f;  // zero pad for decoder K
        }
    }
    #pragma unroll
    for (int o = 16; o > 0; o >>= 1) part += __shfl_down_sync(0xffffffffu, part, o);
    __shared__ float wsum[8];
    int lane = threadIdx.x & 31, wid = threadIdx.x >> 5;
    if (lane == 0) wsum[wid] = part;
    __syncthreads();
    if (wid == 0) {
        float v = (lane < 8) ? wsum[lane] : 0.f;
        #pragma unroll
        for (int o = 4; o > 0; o >>= 1) v += __shfl_down_sync(0xffffffffu, v, o);
        if (lane == 0) atomicAdd(jac_out, v);
    }
}

// ---------------------------------------------------------------------------
extern "C" void kernel_launch(void* const* d_in, const int* in_sizes, int n_in,
                              void* d_out, int out_size) {
    const float* x     = (const float*)d_in[0];
    const float* W_enc = (const float*)d_in[1];
    const float* b_enc = (const float*)d_in[2];
    const float* W_dec = (const float*)d_in[3];
    const float* b_dec = (const float*)d_in[4];
    float* out = (float*)d_out;
    float* jac = out + (out_size - 1);

    float *preact, *yenc;
    cudaGetSymbolAddress((void**)&preact, g_preact);
    cudaGetSymbolAddress((void**)&yenc,  g_yenc);

    cudaFuncSetAttribute(gemm_hmma, cudaFuncAttributeMaxDynamicSharedMemorySize, SMEM_TOTAL);

    // 1) W_enc row norms + jac zero-init
    rownorm_kernel<<<FEAT, 256>>>(W_enc, jac);

    // 2) encoder GEMM: [256,28224] @ [1500,28224]^T, split-K=12 -> 288 CTAs
    {
        dim3 grid((FEAT + BN - 1) / BN, BATCH / BM, SPLITK);   // (12, 2, 12)
        gemm_hmma<<<grid, NTH, SMEM_TOTAL>>>(
            x, W_enc, nullptr, preact,
            FEAT, INSZ, INSZ, INSZ, FEAT,
            ENC_KBLK_PER_SPLIT, ENC_KBLK_TOTAL, 0);
    }

    // 3) bias + sigmoid + jacobian reduction (+ y_enc zero pad)
    enc_epilogue<<<(BATCH * FEAT_PAD + 255) / 256, 256>>>(b_enc, jac);

    // 4) decoder GEMM: [256,1536pad] @ [28224,1500]^T, fused bias+sigmoid
    {
        dim3 grid((INSZ + BN - 1) / BN, BATCH / BM, 1);        // (221, 2, 1)
        gemm_hmma<<<grid, NTH, SMEM_TOTAL>>>(
            yenc, W_dec, b_dec, out,
            INSZ, FEAT_PAD, FEAT, FEAT, INSZ,
            DEC_KBLK, DEC_KBLK, 1);
    }
}